// round 2
// baseline (speedup 1.0000x reference)
#include <cuda_runtime.h>
#include <math.h>

#define S_LEN 2048
#define D_EMB 1024
#define NHEAD 16
#define DH    64
#define BATCH 2
#define MROWS (BATCH * S_LEN)   // 4096
#define LDK   68                // d-major K tile stride (float4-aligned, conflict-free reads)

__device__ float g_q[MROWS * D_EMB];
__device__ float g_k[MROWS * D_EMB];
__device__ float g_v[MROWS * D_EMB];
__device__ float g_attn[MROWS * D_EMB];

// ---------------------------------------------------------------------------
// SGEMM: C[M,N] = A[M,K] @ W[K,N] + bias[N].  128x128 tile, BK=8, 8x8/thread.
// ---------------------------------------------------------------------------
__global__ __launch_bounds__(256, 2)
void gemm_bias_kernel(const float* __restrict__ A, const float* __restrict__ W,
                      const float* __restrict__ bias, float* __restrict__ C,
                      int M, int N, int K)
{
    __shared__ float As[8][128];
    __shared__ float Bs[8][128];
    const int tid = threadIdx.x;
    const int tx = tid & 15;
    const int ty = tid >> 4;
    const int rowBase = blockIdx.y * 128;
    const int colBase = blockIdx.x * 128;

    const int am = tid >> 1;          // 0..127
    const int ak = (tid & 1) << 2;    // 0 or 4
    const int bk = tid >> 5;          // 0..7
    const int bn = (tid & 31) << 2;   // 0..124

    float acc[8][8];
#pragma unroll
    for (int i = 0; i < 8; i++)
#pragma unroll
        for (int j = 0; j < 8; j++) acc[i][j] = 0.f;

    const float* Aptr = A + (size_t)(rowBase + am) * K + ak;
    const float* Wptr = W + (size_t)bk * N + colBase + bn;

    for (int k0 = 0; k0 < K; k0 += 8) {
        float4 av = *(const float4*)(Aptr + k0);
        float4 wv = *(const float4*)(Wptr + (size_t)k0 * N);
        __syncthreads();
        As[ak + 0][am] = av.x;
        As[ak + 1][am] = av.y;
        As[ak + 2][am] = av.z;
        As[ak + 3][am] = av.w;
        *(float4*)&Bs[bk][bn] = wv;
        __syncthreads();
#pragma unroll
        for (int kk = 0; kk < 8; kk++) {
            float a[8], b[8];
            *(float4*)&a[0] = *(const float4*)&As[kk][ty * 8];
            *(float4*)&a[4] = *(const float4*)&As[kk][ty * 8 + 4];
            *(float4*)&b[0] = *(const float4*)&Bs[kk][tx * 8];
            *(float4*)&b[4] = *(const float4*)&Bs[kk][tx * 8 + 4];
#pragma unroll
            for (int i = 0; i < 8; i++)
#pragma unroll
                for (int j = 0; j < 8; j++)
                    acc[i][j] = fmaf(a[i], b[j], acc[i][j]);
        }
    }

    float bsv[8];
    *(float4*)&bsv[0] = *(const float4*)&bias[colBase + tx * 8];
    *(float4*)&bsv[4] = *(const float4*)&bias[colBase + tx * 8 + 4];
#pragma unroll
    for (int i = 0; i < 8; i++) {
        float* crow = C + (size_t)(rowBase + ty * 8 + i) * N + colBase + tx * 8;
        float4 c0, c1;
        c0.x = acc[i][0] + bsv[0]; c0.y = acc[i][1] + bsv[1];
        c0.z = acc[i][2] + bsv[2]; c0.w = acc[i][3] + bsv[3];
        c1.x = acc[i][4] + bsv[4]; c1.y = acc[i][5] + bsv[5];
        c1.z = acc[i][6] + bsv[6]; c1.w = acc[i][7] + bsv[7];
        *(float4*)crow = c0;
        *(float4*)(crow + 4) = c1;
    }
}

// ---------------------------------------------------------------------------
// Flash attention: one CTA per (b, h, 64-row q tile). 256 threads, 4x4/thread.
// smem: Qs[64][64], Kt[64][LDK] (d-major!), Vs[64][64], Ps[64][64]
// ---------------------------------------------------------------------------
#define SMEM_FLOATS (64*64*3 + 64*LDK)
#define SMEM_BYTES  (SMEM_FLOATS * 4)

__global__ __launch_bounds__(256, 2)
void attn_kernel(const float* __restrict__ Q, const float* __restrict__ K,
                 const float* __restrict__ V, float* __restrict__ O)
{
    extern __shared__ float smf[];
    float* Qs = smf;                  // [64][64] row r, col d
    float* Kt = Qs + 64 * 64;         // [64][LDK] row d, col c (transposed)
    float* Vs = Kt + 64 * LDK;        // [64][64] row c, col j
    float* Ps = Vs + 64 * 64;         // [64][64] row r, col c

    const int tid = threadIdx.x;
    const int tx = tid & 15;          // column group (4 cols)
    const int ty = tid >> 4;          // row group (4 rows)
    const int qt = blockIdx.x;
    const int h  = blockIdx.y;
    const int b  = blockIdx.z;

    const size_t qRow0 = (size_t)b * S_LEN + (size_t)qt * 64;
    const int colH = h * DH;

    // load Q tile (coalesced float4, conflict-free stores)
#pragma unroll
    for (int u = 0; u < 4; u++) {
        int s = tid + u * 256;
        int r = s >> 4;
        int dq = (s & 15) << 2;
        float4 v = *(const float4*)&Q[(qRow0 + r) * D_EMB + colH + dq];
        *(float4*)&Qs[r * 64 + dq] = v;
    }

    float o[4][4];
    float mrow[4], lrow[4];
#pragma unroll
    for (int i = 0; i < 4; i++) {
        mrow[i] = -INFINITY;
        lrow[i] = 0.f;
#pragma unroll
        for (int j = 0; j < 4; j++) o[i][j] = 0.f;
    }

    const float scale = 0.03125f; // 1/sqrt(1024)

    for (int kt = 0; kt <= qt; kt++) {
        __syncthreads();  // previous PV done before overwriting Kt/Vs
        const size_t kRow0 = (size_t)b * S_LEN + (size_t)kt * 64;
#pragma unroll
        for (int u = 0; u < 4; u++) {
            int s = tid + u * 256;
            int c = s >> 4;
            int dq = (s & 15) << 2;
            float4 kv = *(const float4*)&K[(kRow0 + c) * D_EMB + colH + dq];
            Kt[(dq + 0) * LDK + c] = kv.x;
            Kt[(dq + 1) * LDK + c] = kv.y;
            Kt[(dq + 2) * LDK + c] = kv.z;
            Kt[(dq + 3) * LDK + c] = kv.w;
            float4 vv = *(const float4*)&V[(kRow0 + c) * D_EMB + colH + dq];
            *(float4*)&Vs[c * 64 + dq] = vv;
        }
        __syncthreads();

        // ---- scores: s4[i][j] = sum_d Q[r0+i][d] * K[c0+j][d] ----
        float s4[4][4];
#pragma unroll
        for (int i = 0; i < 4; i++)
#pragma unroll
            for (int j = 0; j < 4; j++) s4[i][j] = 0.f;

#pragma unroll 4
        for (int d = 0; d < 64; d += 4) {
            float4 q4[4], k4[4];
#pragma unroll
            for (int i = 0; i < 4; i++)
                q4[i] = *(const float4*)&Qs[(ty * 4 + i) * 64 + d];
#pragma unroll
            for (int e = 0; e < 4; e++)
                k4[e] = *(const float4*)&Kt[(d + e) * LDK + tx * 4];
#pragma unroll
            for (int i = 0; i < 4; i++) {
                float q0 = q4[i].x, q1 = q4[i].y, q2 = q4[i].z, q3 = q4[i].w;
#define SDOT(jj, comp)                                      \
                s4[i][jj] = fmaf(q0, k4[0].comp, s4[i][jj]); \
                s4[i][jj] = fmaf(q1, k4[1].comp, s4[i][jj]); \
                s4[i][jj] = fmaf(q2, k4[2].comp, s4[i][jj]); \
                s4[i][jj] = fmaf(q3, k4[3].comp, s4[i][jj]);
                SDOT(0, x) SDOT(1, y) SDOT(2, z) SDOT(3, w)
#undef SDOT
            }
        }

        // causal mask + scale
        if (kt == qt) {
#pragma unroll
            for (int i = 0; i < 4; i++)
#pragma unroll
                for (int j = 0; j < 4; j++) {
                    int rl = ty * 4 + i, cl = tx * 4 + j;
                    s4[i][j] = (cl > rl) ? -INFINITY : s4[i][j] * scale;
                }
        } else {
#pragma unroll
            for (int i = 0; i < 4; i++)
#pragma unroll
                for (int j = 0; j < 4; j++) s4[i][j] *= scale;
        }

        // ---- online softmax (row spread across 16 lanes sharing ty) ----
#pragma unroll
        for (int i = 0; i < 4; i++) {
            float rmax = fmaxf(fmaxf(s4[i][0], s4[i][1]), fmaxf(s4[i][2], s4[i][3]));
            rmax = fmaxf(rmax, __shfl_xor_sync(0xffffffffu, rmax, 8));
            rmax = fmaxf(rmax, __shfl_xor_sync(0xffffffffu, rmax, 4));
            rmax = fmaxf(rmax, __shfl_xor_sync(0xffffffffu, rmax, 2));
            rmax = fmaxf(rmax, __shfl_xor_sync(0xffffffffu, rmax, 1));
            float mnew = fmaxf(mrow[i], rmax);
            float p0 = __expf(s4[i][0] - mnew);
            float p1 = __expf(s4[i][1] - mnew);
            float p2 = __expf(s4[i][2] - mnew);
            float p3 = __expf(s4[i][3] - mnew);
            float sum = (p0 + p1) + (p2 + p3);
            sum += __shfl_xor_sync(0xffffffffu, sum, 8);
            sum += __shfl_xor_sync(0xffffffffu, sum, 4);
            sum += __shfl_xor_sync(0xffffffffu, sum, 2);
            sum += __shfl_xor_sync(0xffffffffu, sum, 1);
            float alpha = __expf(mrow[i] - mnew);
            lrow[i] = lrow[i] * alpha + sum;
            mrow[i] = mnew;
            o[i][0] *= alpha; o[i][1] *= alpha; o[i][2] *= alpha; o[i][3] *= alpha;
            float4 pw = make_float4(p0, p1, p2, p3);
            *(float4*)&Ps[(ty * 4 + i) * 64 + tx * 4] = pw;
        }
        __syncthreads();

        // ---- O += P @ V ----
#pragma unroll 4
        for (int c = 0; c < 64; c += 4) {
            float4 p4[4], v4[4];
#pragma unroll
            for (int i = 0; i < 4; i++)
                p4[i] = *(const float4*)&Ps[(ty * 4 + i) * 64 + c];
#pragma unroll
            for (int e = 0; e < 4; e++)
                v4[e] = *(const float4*)&Vs[(c + e) * 64 + tx * 4];
#pragma unroll
            for (int i = 0; i < 4; i++) {
                float p0 = p4[i].x, p1 = p4[i].y, p2 = p4[i].z, p3 = p4[i].w;
#define PVDOT(jj, comp)                                     \
                o[i][jj] = fmaf(p0, v4[0].comp, o[i][jj]);   \
                o[i][jj] = fmaf(p1, v4[1].comp, o[i][jj]);   \
                o[i][jj] = fmaf(p2, v4[2].comp, o[i][jj]);   \
                o[i][jj] = fmaf(p3, v4[3].comp, o[i][jj]);
                PVDOT(0, x) PVDOT(1, y) PVDOT(2, z) PVDOT(3, w)
#undef PVDOT
            }
        }
    }

    // normalize + write out (fp32)
#pragma unroll
    for (int i = 0; i < 4; i++) {
        float inv = 1.f / lrow[i];
        float4 r;
        r.x = o[i][0] * inv; r.y = o[i][1] * inv;
        r.z = o[i][2] * inv; r.w = o[i][3] * inv;
        *(float4*)&O[(qRow0 + ty * 4 + i) * D_EMB + colH + tx * 4] = r;
    }
}

// ---------------------------------------------------------------------------
extern "C" void kernel_launch(void* const* d_in, const int* in_sizes, int n_in,
                              void* d_out, int out_size)
{
    const float* x  = (const float*)d_in[0];
    const float* Wq = (const float*)d_in[1];
    const float* bq = (const float*)d_in[2];
    const float* Wk = (const float*)d_in[3];
    const float* bk = (const float*)d_in[4];
    const float* Wv = (const float*)d_in[5];
    const float* bv = (const float*)d_in[6];
    const float* Wo = (const float*)d_in[7];
    const float* bo = (const float*)d_in[8];
    float* out = (float*)d_out;

    float *gq, *gk, *gv, *ga;
    cudaGetSymbolAddress((void**)&gq, g_q);
    cudaGetSymbolAddress((void**)&gk, g_k);
    cudaGetSymbolAddress((void**)&gv, g_v);
    cudaGetSymbolAddress((void**)&ga, g_attn);

    cudaFuncSetAttribute(attn_kernel, cudaFuncAttributeMaxDynamicSharedMemorySize,
                         SMEM_BYTES);

    dim3 ggrid(D_EMB / 128, MROWS / 128);   // (8, 32)
    gemm_bias_kernel<<<ggrid, 256>>>(x, Wq, bq, gq, MROWS, D_EMB, D_EMB);
    gemm_bias_kernel<<<ggrid, 256>>>(x, Wk, bk, gk, MROWS, D_EMB, D_EMB);
    gemm_bias_kernel<<<ggrid, 256>>>(x, Wv, bv, gv, MROWS, D_EMB, D_EMB);

    attn_kernel<<<dim3(S_LEN / 64, NHEAD, BATCH), 256, SMEM_BYTES>>>(gq, gk, gv, ga);

    gemm_bias_kernel<<<ggrid, 256>>>(ga, Wo, bo, out, MROWS, D_EMB, D_EMB);
}

// round 5
// speedup vs baseline: 1.4696x; 1.4696x over previous
#include <cuda_runtime.h>
#include <cuda_bf16.h>
#include <math.h>
#include <stdint.h>

#define S_LEN 2048
#define D_EMB 1024
#define NHEAD 16
#define DH    64
#define BATCH 2
#define MROWS (BATCH * S_LEN)   // 4096
#define LDK   68

// ---------------- device scratch ----------------
__device__ float g_q[MROWS * D_EMB];
__device__ float g_k[MROWS * D_EMB];
__device__ float g_v[MROWS * D_EMB];
__device__ float g_attn[MROWS * D_EMB];

__device__ __nv_bfloat16 g_xh[MROWS * D_EMB];
__device__ __nv_bfloat16 g_xl[MROWS * D_EMB];
__device__ __nv_bfloat16 g_ah[MROWS * D_EMB];
__device__ __nv_bfloat16 g_al[MROWS * D_EMB];

__device__ __nv_bfloat16 g_wqh[D_EMB * D_EMB];
__device__ __nv_bfloat16 g_wql[D_EMB * D_EMB];
__device__ __nv_bfloat16 g_wkh[D_EMB * D_EMB];
__device__ __nv_bfloat16 g_wkl[D_EMB * D_EMB];
__device__ __nv_bfloat16 g_wvh[D_EMB * D_EMB];
__device__ __nv_bfloat16 g_wvl[D_EMB * D_EMB];
__device__ __nv_bfloat16 g_woh[D_EMB * D_EMB];
__device__ __nv_bfloat16 g_wol[D_EMB * D_EMB];

// ---------------- helpers ----------------
__device__ __forceinline__ uint32_t smem_to_u32(const void* p) {
    uint32_t a;
    asm("{ .reg .u64 t; cvta.to.shared.u64 t, %1; cvt.u32.u64 %0, t; }"
        : "=r"(a) : "l"(p));
    return a;
}

__device__ __forceinline__ void cp16(uint32_t s, const void* g) {
    asm volatile("cp.async.cg.shared.global [%0], [%1], 16;" :: "r"(s), "l"(g));
}
#define CP_COMMIT() asm volatile("cp.async.commit_group;" ::: "memory")
#define CP_WAIT_ALL() asm volatile("cp.async.wait_group 0;" ::: "memory")

#define LDSM_X4(r0, r1, r2, r3, addr) \
    asm volatile("ldmatrix.sync.aligned.m8n8.x4.shared.b16 {%0,%1,%2,%3}, [%4];" \
        : "=r"(r0), "=r"(r1), "=r"(r2), "=r"(r3) : "r"(addr))

#define MMA16816(c, a, b0, b1) \
    asm volatile("mma.sync.aligned.m16n8k16.row.col.f32.bf16.bf16.f32 " \
        "{%0,%1,%2,%3}, {%4,%5,%6,%7}, {%8,%9}, {%0,%1,%2,%3};" \
        : "+f"((c)[0]), "+f"((c)[1]), "+f"((c)[2]), "+f"((c)[3]) \
        : "r"((a)[0]), "r"((a)[1]), "r"((a)[2]), "r"((a)[3]), "r"(b0), "r"(b1))

// ---------------------------------------------------------------------------
// split fp32 -> bf16 hi/lo
// ---------------------------------------------------------------------------
__global__ __launch_bounds__(256)
void split_bf16_kernel(const float* __restrict__ in,
                       __nv_bfloat16* __restrict__ hi,
                       __nv_bfloat16* __restrict__ lo, int n4)
{
    int idx = blockIdx.x * 256 + threadIdx.x;
    if (idx >= n4) return;
    float4 v = *(const float4*)(in + (size_t)idx * 4);
    __nv_bfloat16 h0 = __float2bfloat16(v.x);
    __nv_bfloat16 h1 = __float2bfloat16(v.y);
    __nv_bfloat16 h2 = __float2bfloat16(v.z);
    __nv_bfloat16 h3 = __float2bfloat16(v.w);
    __nv_bfloat16 l0 = __float2bfloat16(v.x - __bfloat162float(h0));
    __nv_bfloat16 l1 = __float2bfloat16(v.y - __bfloat162float(h1));
    __nv_bfloat16 l2 = __float2bfloat16(v.z - __bfloat162float(h2));
    __nv_bfloat16 l3 = __float2bfloat16(v.w - __bfloat162float(h3));
    __nv_bfloat162* hp = (__nv_bfloat162*)(hi + (size_t)idx * 4);
    __nv_bfloat162* lp = (__nv_bfloat162*)(lo + (size_t)idx * 4);
    hp[0] = __nv_bfloat162(h0, h1);
    hp[1] = __nv_bfloat162(h2, h3);
    lp[0] = __nv_bfloat162(l0, l1);
    lp[1] = __nv_bfloat162(l2, l3);
}

// ---------------------------------------------------------------------------
// transpose + split:  Wt[n,k] = W[k,n]  (1024x1024)
// ---------------------------------------------------------------------------
__global__ __launch_bounds__(256)
void transpose_split_kernel(const float* __restrict__ W,
                            __nv_bfloat16* __restrict__ th,
                            __nv_bfloat16* __restrict__ tl)
{
    __shared__ float t[32][33];
    const int tx = threadIdx.x, ty = threadIdx.y;  // 32 x 8
    const int n0 = blockIdx.x * 32;
    const int k0 = blockIdx.y * 32;
#pragma unroll
    for (int i = 0; i < 4; i++)
        t[ty + i * 8][tx] = W[(size_t)(k0 + ty + i * 8) * D_EMB + n0 + tx];
    __syncthreads();
#pragma unroll
    for (int i = 0; i < 4; i++) {
        int n = n0 + ty + i * 8;
        int k = k0 + tx;
        float v = t[tx][ty + i * 8];
        __nv_bfloat16 h = __float2bfloat16(v);
        __nv_bfloat16 l = __float2bfloat16(v - __bfloat162float(h));
        th[(size_t)n * D_EMB + k] = h;
        tl[(size_t)n * D_EMB + k] = l;
    }
}

// ---------------------------------------------------------------------------
// mma.sync GEMM: C[4096,1024] = (Ah+Al) @ (Wh+Wl)^T + bias
//   CTA tile 128x256, 8 warps (2x4), warp tile 64x64, BK=32, 2-stage cp.async.
//   smem rows padded to 80 B (40 bf16) -> conflict-free ldmatrix.
// ---------------------------------------------------------------------------
#define ROWB      80                       // bytes per smem row (32 bf16 + pad)
#define STAGE_A   (128 * ROWB)             // 10240 B per A half
#define STAGE_B   (256 * ROWB)             // 20480 B per B half
#define STAGE_TOTAL (2 * STAGE_A + 2 * STAGE_B)   // 61440
#define GEMM_SMEM (2 * STAGE_TOTAL)        // 122880

__device__ __forceinline__ void load_stage(
    const __nv_bfloat16* __restrict__ Ah, const __nv_bfloat16* __restrict__ Al,
    const __nv_bfloat16* __restrict__ Bh, const __nv_bfloat16* __restrict__ Bl,
    int rowBase, int colBase, int k0, uint32_t sbase, int tid)
{
#pragma unroll
    for (int i = 0; i < 2; i++) {
        int c = tid * 2 + i;               // 0..511
        int r = c >> 2, kc = c & 3;
        size_t goff = (size_t)(rowBase + r) * D_EMB + k0 + kc * 8;
        uint32_t soff = r * ROWB + kc * 16;
        cp16(sbase + soff, Ah + goff);
        cp16(sbase + STAGE_A + soff, Al + goff);
    }
#pragma unroll
    for (int i = 0; i < 4; i++) {
        int c = tid * 4 + i;               // 0..1023
        int r = c >> 2, kc = c & 3;
        size_t goff = (size_t)(colBase + r) * D_EMB + k0 + kc * 8;
        uint32_t soff = r * ROWB + kc * 16;
        cp16(sbase + 2 * STAGE_A + soff, Bh + goff);
        cp16(sbase + 2 * STAGE_A + STAGE_B + soff, Bl + goff);
    }
}

__global__ __launch_bounds__(256, 1)
void mma_gemm_bias_kernel(const __nv_bfloat16* __restrict__ Ah,
                          const __nv_bfloat16* __restrict__ Al,
                          const __nv_bfloat16* __restrict__ Wh,
                          const __nv_bfloat16* __restrict__ Wl,
                          const float* __restrict__ bias,
                          float* __restrict__ C)
{
    extern __shared__ char smem[];
    const uint32_t sbase = smem_to_u32(smem);
    const int tid = threadIdx.x;
    const int wid = tid >> 5;
    const int lid = tid & 31;
    const int wm = wid & 1;                // 2 M warp-tiles
    const int wn = wid >> 1;               // 4 N warp-tiles
    const int rowBase = blockIdx.y * 128;
    const int colBase = blockIdx.x * 256;

    float c[4][8][4];
#pragma unroll
    for (int i = 0; i < 4; i++)
#pragma unroll
        for (int j = 0; j < 8; j++)
#pragma unroll
            for (int q = 0; q < 4; q++) c[i][j][q] = 0.f;

    // ldmatrix lane addressing (byte offsets within A/B halves)
    const uint32_t a_lane = (uint32_t)((wm * 64 + (lid & 15)) * ROWB + (lid >> 4) * 16);
    const int bmi = lid >> 3, bwi = lid & 7;
    const uint32_t b_lane = (uint32_t)((wn * 64 + ((bmi >> 1) << 3) + bwi) * ROWB
                                       + (bmi & 1) * 16);

    load_stage(Ah, Al, Wh, Wl, rowBase, colBase, 0, sbase, tid);
    CP_COMMIT();

    for (int ch = 0; ch < 32; ch++) {
        CP_WAIT_ALL();
        __syncthreads();
        if (ch + 1 < 32) {
            load_stage(Ah, Al, Wh, Wl, rowBase, colBase, (ch + 1) * 32,
                       sbase + ((ch + 1) & 1) * STAGE_TOTAL, tid);
            CP_COMMIT();
        }
        const uint32_t sA = sbase + (ch & 1) * STAGE_TOTAL;
        const uint32_t sB = sA + 2 * STAGE_A;

#pragma unroll
        for (int kk = 0; kk < 2; kk++) {
            const uint32_t kb = kk * 32;   // byte offset of this k16 within row
            uint32_t af[4][4], bh[4][4], bl[4][4];
#pragma unroll
            for (int mt = 0; mt < 4; mt++)
                LDSM_X4(af[mt][0], af[mt][1], af[mt][2], af[mt][3],
                        sA + a_lane + mt * (16 * ROWB) + kb);
#pragma unroll
            for (int np = 0; np < 4; np++)
                LDSM_X4(bh[np][0], bh[np][1], bh[np][2], bh[np][3],
                        sB + b_lane + np * (16 * ROWB) + kb);
#pragma unroll
            for (int np = 0; np < 4; np++)
                LDSM_X4(bl[np][0], bl[np][1], bl[np][2], bl[np][3],
                        sB + STAGE_B + b_lane + np * (16 * ROWB) + kb);

            // Ah*Bh + Ah*Bl
#pragma unroll
            for (int mt = 0; mt < 4; mt++)
#pragma unroll
                for (int np = 0; np < 4; np++) {
                    MMA16816(c[mt][np * 2],     af[mt], bh[np][0], bh[np][1]);
                    MMA16816(c[mt][np * 2 + 1], af[mt], bh[np][2], bh[np][3]);
                    MMA16816(c[mt][np * 2],     af[mt], bl[np][0], bl[np][1]);
                    MMA16816(c[mt][np * 2 + 1], af[mt], bl[np][2], bl[np][3]);
                }
            // Al*Bh
#pragma unroll
            for (int mt = 0; mt < 4; mt++)
                LDSM_X4(af[mt][0], af[mt][1], af[mt][2], af[mt][3],
                        sA + STAGE_A + a_lane + mt * (16 * ROWB) + kb);
#pragma unroll
            for (int mt = 0; mt < 4; mt++)
#pragma unroll
                for (int np = 0; np < 4; np++) {
                    MMA16816(c[mt][np * 2],     af[mt], bh[np][0], bh[np][1]);
                    MMA16816(c[mt][np * 2 + 1], af[mt], bh[np][2], bh[np][3]);
                }
        }
    }

    // epilogue
    const int r0 = rowBase + wm * 64 + (lid >> 2);
    const int c0 = colBase + wn * 64 + (lid & 3) * 2;
#pragma unroll
    for (int mt = 0; mt < 4; mt++) {
#pragma unroll
        for (int nt = 0; nt < 8; nt++) {
            const int row = r0 + mt * 16;
            const int col = c0 + nt * 8;
            float2 bv = *(const float2*)&bias[col];
            float2 v0, v1;
            v0.x = c[mt][nt][0] + bv.x; v0.y = c[mt][nt][1] + bv.y;
            v1.x = c[mt][nt][2] + bv.x; v1.y = c[mt][nt][3] + bv.y;
            *(float2*)&C[(size_t)row * D_EMB + col] = v0;
            *(float2*)&C[(size_t)(row + 8) * D_EMB + col] = v1;
        }
    }
}

// ---------------------------------------------------------------------------
// Flash attention (unchanged, fp32 SIMT)
// ---------------------------------------------------------------------------
#define SMEM_FLOATS (64*64*3 + 64*LDK)
#define ATTN_SMEM_BYTES  (SMEM_FLOATS * 4)

__global__ __launch_bounds__(256, 2)
void attn_kernel(const float* __restrict__ Q, const float* __restrict__ K,
                 const float* __restrict__ V, float* __restrict__ O)
{
    extern __shared__ float smf[];
    float* Qs = smf;
    float* Kt = Qs + 64 * 64;
    float* Vs = Kt + 64 * LDK;
    float* Ps = Vs + 64 * 64;

    const int tid = threadIdx.x;
    const int tx = tid & 15;
    const int ty = tid >> 4;
    const int qt = blockIdx.x;
    const int h  = blockIdx.y;
    const int b  = blockIdx.z;

    const size_t qRow0 = (size_t)b * S_LEN + (size_t)qt * 64;
    const int colH = h * DH;

#pragma unroll
    for (int u = 0; u < 4; u++) {
        int s = tid + u * 256;
        int r = s >> 4;
        int dq = (s & 15) << 2;
        float4 v = *(const float4*)&Q[(qRow0 + r) * D_EMB + colH + dq];
        *(float4*)&Qs[r * 64 + dq] = v;
    }

    float o[4][4];
    float mrow[4], lrow[4];
#pragma unroll
    for (int i = 0; i < 4; i++) {
        mrow[i] = -INFINITY;
        lrow[i] = 0.f;
#pragma unroll
        for (int j = 0; j < 4; j++) o[i][j] = 0.f;
    }

    const float scale = 0.03125f;

    for (int kt = 0; kt <= qt; kt++) {
        __syncthreads();
        const size_t kRow0 = (size_t)b * S_LEN + (size_t)kt * 64;
#pragma unroll
        for (int u = 0; u < 4; u++) {
            int s = tid + u * 256;
            int c2 = s >> 4;
            int dq = (s & 15) << 2;
            float4 kv = *(const float4*)&K[(kRow0 + c2) * D_EMB + colH + dq];
            Kt[(dq + 0) * LDK + c2] = kv.x;
            Kt[(dq + 1) * LDK + c2] = kv.y;
            Kt[(dq + 2) * LDK + c2] = kv.z;
            Kt[(dq + 3) * LDK + c2] = kv.w;
            float4 vv = *(const float4*)&V[(kRow0 + c2) * D_EMB + colH + dq];
            *(float4*)&Vs[c2 * 64 + dq] = vv;
        }
        __syncthreads();

        float s4[4][4];
#pragma unroll
        for (int i = 0; i < 4; i++)
#pragma unroll
            for (int j = 0; j < 4; j++) s4[i][j] = 0.f;

#pragma unroll 4
        for (int d = 0; d < 64; d += 4) {
            float4 q4[4], k4[4];
#pragma unroll
            for (int i = 0; i < 4; i++)
                q4[i] = *(const float4*)&Qs[(ty * 4 + i) * 64 + d];
#pragma unroll
            for (int e = 0; e < 4; e++)
                k4[e] = *(const float4*)&Kt[(d + e) * LDK + tx * 4];
#pragma unroll
            for (int i = 0; i < 4; i++) {
                float q0 = q4[i].x, q1 = q4[i].y, q2 = q4[i].z, q3 = q4[i].w;
#define SDOT(jj, comp)                                      \
                s4[i][jj] = fmaf(q0, k4[0].comp, s4[i][jj]); \
                s4[i][jj] = fmaf(q1, k4[1].comp, s4[i][jj]); \
                s4[i][jj] = fmaf(q2, k4[2].comp, s4[i][jj]); \
                s4[i][jj] = fmaf(q3, k4[3].comp, s4[i][jj]);
                SDOT(0, x) SDOT(1, y) SDOT(2, z) SDOT(3, w)
#undef SDOT
            }
        }

        if (kt == qt) {
#pragma unroll
            for (int i = 0; i < 4; i++)
#pragma unroll
                for (int j = 0; j < 4; j++) {
                    int rl = ty * 4 + i, cl = tx * 4 + j;
                    s4[i][j] = (cl > rl) ? -INFINITY : s4[i][j] * scale;
                }
        } else {
#pragma unroll
            for (int i = 0; i < 4; i++)
#pragma unroll
                for (int j = 0; j < 4; j++) s4[i][j] *= scale;
        }

#pragma unroll
        for (int i = 0; i < 4; i++) {
            float rmax = fmaxf(fmaxf(s4[i][0], s4[i][1]), fmaxf(s4[i][2], s4[i][3]));
            rmax = fmaxf(rmax, __shfl_xor_sync(0xffffffffu, rmax, 8));
            rmax = fmaxf(rmax, __shfl_xor_sync(0xffffffffu, rmax, 4));
            rmax = fmaxf(rmax, __shfl_xor_sync(0xffffffffu, rmax, 2));
            rmax = fmaxf(rmax, __shfl_xor_sync(0xffffffffu, rmax, 1));
            float mnew = fmaxf(mrow[i], rmax);
            float p0 = __expf(s4[i][0] - mnew);
            float p1 = __expf(s4[i][1] - mnew);
            float p2 = __expf(s4[i][2] - mnew);
            float p3 = __expf(s4[i][3] - mnew);
            float sum = (p0 + p1) + (p2 + p3);
            sum += __shfl_xor_sync(0xffffffffu, sum, 8);
            sum += __shfl_xor_sync(0xffffffffu, sum, 4);
            sum += __shfl_xor_sync(0xffffffffu, sum, 2);
            sum += __shfl_xor_sync(0xffffffffu, sum, 1);
            float alpha = __expf(mrow[i] - mnew);
            lrow[i] = lrow[i] * alpha + sum;
            mrow[i] = mnew;
            o[i][0] *= alpha; o[i][1] *= alpha; o[i][2] *= alpha; o[i][3] *= alpha;
            float4 pw = make_float4(p0, p1, p2, p3);
            *(float4*)&Ps[(ty * 4 + i) * 64 + tx * 4] = pw;
        }
        __syncthreads();

#pragma unroll 4
        for (int c2 = 0; c2 < 64; c2 += 4) {
            float4 p4[4], v4[4];
#pragma unroll
            for (int i = 0; i < 4; i++)
                p4[i] = *(const float4*)&Ps[(ty * 4 + i) * 64 + c2];
#pragma unroll
            for (int e = 0; e < 4; e++)
                v4[e] = *(const float4*)&Vs[(c2 + e) * 64 + tx * 4];
#pragma unroll
            for (int i = 0; i < 4; i++) {
                float p0 = p4[i].x, p1 = p4[i].y, p2 = p4[i].z, p3 = p4[i].w;
#define PVDOT(jj, comp)                                     \
                o[i][jj] = fmaf(p0, v4[0].comp, o[i][jj]);   \
                o[i][jj] = fmaf(p1, v4[1].comp, o[i][jj]);   \
                o[i][jj] = fmaf(p2, v4[2].comp, o[i][jj]);   \
                o[i][jj] = fmaf(p3, v4[3].comp, o[i][jj]);
                PVDOT(0, x) PVDOT(1, y) PVDOT(2, z) PVDOT(3, w)
#undef PVDOT
            }
        }
    }

#pragma unroll
    for (int i = 0; i < 4; i++) {
        float inv = 1.f / lrow[i];
        float4 r;
        r.x = o[i][0] * inv; r.y = o[i][1] * inv;
        r.z = o[i][2] * inv; r.w = o[i][3] * inv;
        *(float4*)&O[(qRow0 + ty * 4 + i) * D_EMB + colH + tx * 4] = r;
    }
}

// ---------------------------------------------------------------------------
extern "C" void kernel_launch(void* const* d_in, const int* in_sizes, int n_in,
                              void* d_out, int out_size)
{
    const float* x  = (const float*)d_in[0];
    const float* Wq = (const float*)d_in[1];
    const float* bq = (const float*)d_in[2];
    const float* Wk = (const float*)d_in[3];
    const float* bk = (const float*)d_in[4];
    const float* Wv = (const float*)d_in[5];
    const float* bv = (const float*)d_in[6];
    const float* Wo = (const float*)d_in[7];
    const float* bo = (const float*)d_in[8];
    float* out = (float*)d_out;

    float *gq, *gk, *gv, *ga;
    cudaGetSymbolAddress((void**)&gq, g_q);
    cudaGetSymbolAddress((void**)&gk, g_k);
    cudaGetSymbolAddress((void**)&gv, g_v);
    cudaGetSymbolAddress((void**)&ga, g_attn);
    __nv_bfloat16 *xh, *xl, *ah, *al;
    cudaGetSymbolAddress((void**)&xh, g_xh);
    cudaGetSymbolAddress((void**)&xl, g_xl);
    cudaGetSymbolAddress((void**)&ah, g_ah);
    cudaGetSymbolAddress((void**)&al, g_al);
    __nv_bfloat16 *wqh, *wql, *wkh, *wkl, *wvh, *wvl, *woh, *wol;
    cudaGetSymbolAddress((void**)&wqh, g_wqh);
    cudaGetSymbolAddress((void**)&wql, g_wql);
    cudaGetSymbolAddress((void**)&wkh, g_wkh);
    cudaGetSymbolAddress((void**)&wkl, g_wkl);
    cudaGetSymbolAddress((void**)&wvh, g_wvh);
    cudaGetSymbolAddress((void**)&wvl, g_wvl);
    cudaGetSymbolAddress((void**)&woh, g_woh);
    cudaGetSymbolAddress((void**)&wol, g_wol);

    cudaFuncSetAttribute(attn_kernel, cudaFuncAttributeMaxDynamicSharedMemorySize,
                         ATTN_SMEM_BYTES);
    cudaFuncSetAttribute(mma_gemm_bias_kernel,
                         cudaFuncAttributeMaxDynamicSharedMemorySize, GEMM_SMEM);

    const int n4 = MROWS * D_EMB / 4;
    dim3 tgrid(32, 32), tblk(32, 8);
    dim3 ggrid(D_EMB / 256, MROWS / 128);       // (4, 32) = 128 CTAs

    split_bf16_kernel<<<(n4 + 255) / 256, 256>>>(x, xh, xl, n4);
    transpose_split_kernel<<<tgrid, tblk>>>(Wq, wqh, wql);
    transpose_split_kernel<<<tgrid, tblk>>>(Wk, wkh, wkl);
    transpose_split_kernel<<<tgrid, tblk>>>(Wv, wvh, wvl);
    transpose_split_kernel<<<tgrid, tblk>>>(Wo, woh, wol);

    mma_gemm_bias_kernel<<<ggrid, 256, GEMM_SMEM>>>(xh, xl, wqh, wql, bq, gq);
    mma_gemm_bias_kernel<<<ggrid, 256, GEMM_SMEM>>>(xh, xl, wkh, wkl, bk, gk);
    mma_gemm_bias_kernel<<<ggrid, 256, GEMM_SMEM>>>(xh, xl, wvh, wvl, bv, gv);

    attn_kernel<<<dim3(S_LEN / 64, NHEAD, BATCH), 256, ATTN_SMEM_BYTES>>>(gq, gk, gv, ga);

    split_bf16_kernel<<<(n4 + 255) / 256, 256>>>(ga, ah, al, n4);
    mma_gemm_bias_kernel<<<ggrid, 256, GEMM_SMEM>>>(ah, al, woh, wol, bo, out);
}